// round 13
// baseline (speedup 1.0000x reference)
#include <cuda_runtime.h>
#include <cuda_fp16.h>
#include <cstdint>

// B=128, T=512, DIM=256, E=512, H=512
// out = hidden_seq(33554432) + h_last at 33554432 + c_last at 33619968

__device__ __align__(16) float g_wcomb[2048 * 256];
__device__ __align__(16) float g_bcomb[2048];
__device__ __align__(16) float g_xs[134217728];      // [t][gate][b][h] fp32
__device__ __align__(16) __half g_xh[16777216];      // X fp16 [65536][256]
__device__ __align__(16) __half g_wch[524288];       // Wcomb hi [2048][256]
__device__ __align__(16) __half g_wcl[524288];       // Wcomb lo
__device__ __align__(16) __half g_rph[1048576];      // R fp16 packed [2048][512]; row=hc*64+gate*16+j <-> Rgate[hc*16+j]
__device__ __align__(16) __half g_hh[2][65536];      // h fp16 double buffer [b][k]
__device__ unsigned g_cnt4[128];                     // 4 group counters, stride 32 (128B apart)

// ---------- helpers ----------
__device__ __forceinline__ uint32_t smem_u32(const void* p) {
    uint32_t a;
    asm("{ .reg .u64 t; cvta.to.shared.u64 t, %1; cvt.u32.u64 %0, t; }" : "=r"(a) : "l"(p));
    return a;
}
__device__ __forceinline__ void ldm_x4(uint32_t* a, uint32_t addr) {
    asm volatile("ldmatrix.sync.aligned.m8n8.x4.shared.b16 {%0,%1,%2,%3}, [%4];"
                 : "=r"(a[0]), "=r"(a[1]), "=r"(a[2]), "=r"(a[3]) : "r"(addr));
}
__device__ __forceinline__ void mma16816(float* d, const uint32_t* a, uint32_t b0, uint32_t b1) {
    asm volatile("mma.sync.aligned.m16n8k16.row.col.f32.f16.f16.f32 "
                 "{%0,%1,%2,%3},{%4,%5,%6,%7},{%8,%9},{%0,%1,%2,%3};"
                 : "+f"(d[0]), "+f"(d[1]), "+f"(d[2]), "+f"(d[3])
                 : "r"(a[0]), "r"(a[1]), "r"(a[2]), "r"(a[3]), "r"(b0), "r"(b1));
}
__device__ __forceinline__ void cpa16(uint32_t saddr, const void* g) {
    asm volatile("cp.async.cg.shared.global [%0], [%1], 16;" :: "r"(saddr), "l"(g));
}
#define CP_COMMIT() asm volatile("cp.async.commit_group;" ::: "memory")
#define CP_WAIT(N)  asm volatile("cp.async.wait_group %0;" :: "n"(N) : "memory")

__device__ __forceinline__ void split1(float v, __half& h, __half& l) {
    h = __float2half_rn(v);
    l = __float2half_rn(v - __half2float(h));
}

// ---------- prep kernels ----------
__global__ void reset_kernel() {
    if (threadIdx.x < 128) g_cnt4[threadIdx.x] = 0u;
}

__global__ void wcomb_kernel(const float* __restrict__ Wi, const float* __restrict__ Wf,
                             const float* __restrict__ Wg, const float* __restrict__ Wo,
                             const float* __restrict__ We) {
    __shared__ float As[16][65];
    __shared__ float Bs[16][65];
    const int bm = blockIdx.y * 64, bn = blockIdx.x * 64, tid = threadIdx.x;
    const int tx = tid % 16, ty = tid / 16;
    float acc[4][4] = {};
    for (int k0 = 0; k0 < 512; k0 += 16) {
        for (int i = tid; i < 1024; i += 256) {
            int r = i / 16, kk = i % 16, row = bm + r, gate = row >> 9, h = row & 511;
            const float* W = (gate == 0) ? Wi : (gate == 1) ? Wf : (gate == 2) ? Wg : Wo;
            As[kk][r] = W[h * 512 + k0 + kk];
        }
        for (int i = tid; i < 1024; i += 256) {
            int kk = i / 64, c = i % 64;
            Bs[kk][c] = We[(k0 + kk) * 256 + bn + c];
        }
        __syncthreads();
#pragma unroll
        for (int kk = 0; kk < 16; kk++) {
            float a[4], b[4];
#pragma unroll
            for (int i = 0; i < 4; i++) a[i] = As[kk][ty * 4 + i];
#pragma unroll
            for (int j = 0; j < 4; j++) b[j] = Bs[kk][tx * 4 + j];
#pragma unroll
            for (int i = 0; i < 4; i++)
#pragma unroll
                for (int j = 0; j < 4; j++) acc[i][j] += a[i] * b[j];
        }
        __syncthreads();
    }
#pragma unroll
    for (int i = 0; i < 4; i++)
#pragma unroll
        for (int j = 0; j < 4; j++)
            g_wcomb[(bm + ty * 4 + i) * 256 + bn + tx * 4 + j] = acc[i][j];
}

__global__ void bcomb_kernel(const float* __restrict__ Wi, const float* __restrict__ Wf,
                             const float* __restrict__ Wg, const float* __restrict__ Wo,
                             const float* __restrict__ be,
                             const float* __restrict__ bi, const float* __restrict__ bf,
                             const float* __restrict__ bg, const float* __restrict__ bo) {
    int r = blockIdx.x * 256 + threadIdx.x;
    if (r >= 2048) return;
    int gate = r >> 9, h = r & 511;
    const float* W = (gate == 0) ? Wi : (gate == 1) ? Wf : (gate == 2) ? Wg : Wo;
    const float* bb = (gate == 0) ? bi : (gate == 1) ? bf : (gate == 2) ? bg : bo;
    float s = 0.f;
    for (int e = 0; e < 512; e++) s += W[h * 512 + e] * be[e];
    g_bcomb[r] = s + bb[h];
}

__global__ void split_x_kernel(const float* __restrict__ x) {
    size_t i = ((size_t)blockIdx.x * 256 + threadIdx.x) * 4;
    float4 v = *(const float4*)(x + i);
    ((__half2*)(g_xh + i))[0] = __floats2half2_rn(v.x, v.y);
    ((__half2*)(g_xh + i))[1] = __floats2half2_rn(v.z, v.w);
}
__global__ void split_w_kernel() {
    size_t i = ((size_t)blockIdx.x * 256 + threadIdx.x) * 4;
    float4 v = *(const float4*)(g_wcomb + i);
    __half h0, h1, h2, h3, l0, l1, l2, l3;
    split1(v.x, h0, l0); split1(v.y, h1, l1); split1(v.z, h2, l2); split1(v.w, h3, l3);
    ((__half2*)(g_wch + i))[0] = __halves2half2(h0, h1);
    ((__half2*)(g_wch + i))[1] = __halves2half2(h2, h3);
    ((__half2*)(g_wcl + i))[0] = __halves2half2(l0, l1);
    ((__half2*)(g_wcl + i))[1] = __halves2half2(l2, l3);
}
__global__ void split_h0_kernel(const float* __restrict__ h0) {
    size_t i = ((size_t)blockIdx.x * 256 + threadIdx.x) * 4;
    float4 v = *(const float4*)(h0 + i);
    ((__half2*)(g_hh[0] + i))[0] = __floats2half2_rn(v.x, v.y);
    ((__half2*)(g_hh[0] + i))[1] = __floats2half2_rn(v.z, v.w);
}
__global__ void split_R_kernel(const float* __restrict__ Ri, const float* __restrict__ Rf,
                               const float* __restrict__ Rg, const float* __restrict__ Ro) {
    size_t i = (size_t)blockIdx.x * 256 + threadIdx.x;   // 262144 quads
    int r = (int)(i >> 7), k = (int)(i & 127) * 4;
    int hc = r >> 6, w = r & 63, gate = w >> 4, j = w & 15;
    int h = hc * 16 + j;
    const float* R = (gate == 0) ? Ri : (gate == 1) ? Rf : (gate == 2) ? Rg : Ro;
    float4 v = *(const float4*)(R + (size_t)h * 512 + k);
    ((__half2*)(g_rph + (size_t)r * 512 + k))[0] = __floats2half2_rn(v.x, v.y);
    ((__half2*)(g_rph + (size_t)r * 512 + k))[1] = __floats2half2_rn(v.z, v.w);
}

// ---------- xs GEMM: X fp16 x W split-fp16 (2 terms, unchanged from R12) ----------
#define XS_SMEM 110592
__global__ void __launch_bounds__(256) xs_mm_kernel() {
    extern __shared__ __half xsm[];
    uint32_t sb = smem_u32(xsm);
    const int tid = threadIdx.x, lane = tid & 31, wid = tid >> 5;
    const int bn = blockIdx.x * 128, bm = blockIdx.y * 128;
    const int wm = (wid & 1) * 64, wn = (wid >> 1) * 32;

    float acc[4][4][4] = {};

    auto load_kc = [&](int kc) {
        uint32_t base = (kc & 1) * 27648;
        const int kcol = kc * 64;
#pragma unroll
        for (int q = 0; q < 4; q++) {
            int idx = tid + q * 256, r = idx >> 3, u = idx & 7;
            size_t ga = (size_t)(bm + r) * 256 + kcol + u * 8;
            size_t gb = (size_t)(bn + r) * 256 + kcol + u * 8;
            uint32_t so = (base + r * 72 + u * 8) * 2;
            cpa16(sb + so, g_xh + ga);
            cpa16(sb + so + 18432, g_wch + gb);
            cpa16(sb + so + 36864, g_wcl + gb);
        }
    };

    load_kc(0);
    CP_COMMIT();
    for (int kc = 0; kc < 4; kc++) {
        if (kc < 3) { load_kc(kc + 1); CP_COMMIT(); CP_WAIT(1); }
        else        { CP_WAIT(0); }
        __syncthreads();
        const uint32_t ah = sb + ((kc & 1) * 27648) * 2;
        const uint32_t bhb = ah + 18432, blb = ah + 36864;
        const uint32_t aoff = (wm + (lane & 15)) * 72 + ((lane >> 4) << 3);
        const uint32_t boff0 = (wn + ((lane >> 4) << 3) + (lane & 7)) * 72 + (((lane >> 3) & 1) << 3);
        const uint32_t boff1 = boff0 + 16 * 72;
#pragma unroll
        for (int kk = 0; kk < 64; kk += 16) {
            uint32_t bh01[4], bh23[4], bl01[4], bl23[4];
            ldm_x4(bh01, bhb + (boff0 + kk) * 2);
            ldm_x4(bh23, bhb + (boff1 + kk) * 2);
            ldm_x4(bl01, blb + (boff0 + kk) * 2);
            ldm_x4(bl23, blb + (boff1 + kk) * 2);
#pragma unroll
            for (int i = 0; i < 4; i++) {
                uint32_t ahi[4];
                ldm_x4(ahi, ah + (aoff + i * 16 * 72 + kk) * 2);
                mma16816(acc[i][0], ahi, bh01[0], bh01[1]);
                mma16816(acc[i][1], ahi, bh01[2], bh01[3]);
                mma16816(acc[i][2], ahi, bh23[0], bh23[1]);
                mma16816(acc[i][3], ahi, bh23[2], bh23[3]);
                mma16816(acc[i][0], ahi, bl01[0], bl01[1]);
                mma16816(acc[i][1], ahi, bl01[2], bl01[3]);
                mma16816(acc[i][2], ahi, bl23[0], bl23[1]);
                mma16816(acc[i][3], ahi, bl23[2], bl23[3]);
            }
        }
        __syncthreads();
    }

    const int gate = bn >> 9, hb = bn & 511;
#pragma unroll
    for (int f = 0; f < 4; f++) {
        int nl = wn + f * 8 + (lane & 3) * 2;
        float b0v = g_bcomb[bn + nl], b1v = g_bcomb[bn + nl + 1];
#pragma unroll
        for (int i = 0; i < 4; i++) {
            int m0 = bm + wm + i * 16 + (lane >> 2);
#pragma unroll
            for (int rr = 0; rr < 2; rr++) {
                int m = m0 + rr * 8;
                int t = m & 511, b = m >> 9;
                float2 v = make_float2(acc[i][f][rr * 2 + 0] + b0v, acc[i][f][rr * 2 + 1] + b1v);
                *(float2*)(g_xs + (((size_t)t * 4 + gate) * 128 + b) * 512 + hb + nl) = v;
            }
        }
    }
}

// ---------- persistent scan: h fp16 x R fp16, K-split warps, prefetched xs ----------
// 128 blocks x 256 thr. Warp = (wm 2) x (wn 2 of N32) x (kh 2 of k64-per-chunk-half).
// smem halves: R @0 (64x520), h @33280 (32x520).
// bytes: accs @99840 (2 x 64x33 f32 = 16896), xsbuf @116736 (2 x 8192). total 133120.
#define HS_OFF 33280
#define ACC_B 99840
#define XSB_B 116736
#define SC_SMEM 133120
__global__ void __launch_bounds__(256, 1) scan_mm_kernel(const float* __restrict__ c0,
                                                         float* __restrict__ out) {
    extern __shared__ __half ssm[];
    uint32_t sb = smem_u32(ssm);
    const int tid = threadIdx.x, lane = tid & 31, wid = tid >> 5;
    const int bchunk = blockIdx.x >> 5, hchunk = blockIdx.x & 31;
    const int b0 = bchunk * 32;
    const int wm = (wid & 1) * 16, wn = ((wid >> 1) & 1) * 32, kh = wid >> 2;
    float* accs = (float*)((char*)ssm + ACC_B) + kh * 2112;   // my partial buffer
    float* acc0 = (float*)((char*)ssm + ACC_B);
    float* acc1 = acc0 + 2112;

    // R resident (fp16)
#pragma unroll
    for (int q = 0; q < 16; q++) {
        int idx = tid + q * 256;
        int r = idx >> 6, u = idx & 63;
        const __half* src = g_rph + (size_t)(hchunk * 64 + r) * 512 + u * 8;
        *(uint4*)((char*)ssm + (r * 520 + u * 8) * 2) = *(const uint4*)src;
    }
    __syncthreads();

    float creg[2], hlast[2];
#pragma unroll
    for (int s = 0; s < 2; s++) {
        int q = tid + s * 256;
        int bl = q >> 4, hl = q & 15;
        creg[s] = c0[(b0 + bl) * 512 + hchunk * 16 + hl];
        hlast[s] = 0.f;
    }

    const uint32_t arow = (wm + (lane & 15)) * 520 + ((lane >> 4) << 3);
    const uint32_t brow = (wn + ((lane >> 4) << 3) + (lane & 7)) * 520 + (((lane >> 3) & 1) << 3);
    const uint32_t brow2 = brow + 16 * 520;

    auto prefetch_xs = [&](int t, int buf) {
#pragma unroll
        for (int q = 0; q < 2; q++) {
            int idx = tid + q * 256;
            int gate = idx >> 7, w = idx & 127, bl = w >> 2, p = w & 3;
            const float* src = g_xs + (size_t)t * 262144 + (size_t)gate * 65536
                             + (size_t)(b0 + bl) * 512 + hchunk * 16 + p * 4;
            cpa16(sb + XSB_B + buf * 8192 + ((gate * 32 + bl) * 16 + p * 4) * 4, src);
        }
    };

    // preload xs(0) into buffer 0  -> pending group invariant = 1 at loop top
    prefetch_xs(0, 0);
    CP_COMMIT();

    for (int t = 0; t < 512; t++) {
        const __half* hhp = g_hh[t & 1];
        float* xsf = (float*)((char*)ssm + XSB_B + (t & 1) * 8192);

        auto load_h = [&](int c) {
#pragma unroll
            for (int q = 0; q < 2; q++) {
                int idx = tid + q * 256;
                int r = idx >> 4, u = idx & 15;
                const __half* src = hhp + (size_t)(b0 + r) * 512 + c * 128 + u * 8;
                cpa16(sb + (HS_OFF + r * 520 + c * 128 + u * 8) * 2, src);
            }
        };
        load_h(0); CP_COMMIT();
        load_h(1); CP_COMMIT();
        load_h(2); CP_COMMIT();
        load_h(3); CP_COMMIT();

        float acc[4][4] = {};
        auto chunk = [&](int c) {
            const int kb = c * 128 + kh * 64;   // each warp does its 64-k half of the chunk
#pragma unroll
            for (int k8 = 0; k8 < 4; k8++) {
                int kk = kb + k8 * 16;
                uint32_t ahi[4], bA[4], bB[4];
                ldm_x4(ahi, sb + (HS_OFF + arow + kk) * 2);
                ldm_x4(bA, sb + (brow + kk) * 2);
                ldm_x4(bB, sb + (brow2 + kk) * 2);
                mma16816(acc[0], ahi, bA[0], bA[1]);
                mma16816(acc[1], ahi, bA[2], bA[3]);
                mma16816(acc[2], ahi, bB[0], bB[1]);
                mma16816(acc[3], ahi, bB[2], bB[3]);
            }
        };
        // pending at this point: xs(t), h0, h1, h2, h3
        CP_WAIT(3); __syncthreads(); chunk(0);   // drains xs(t) + h0
        CP_WAIT(2); __syncthreads(); chunk(1);
        CP_WAIT(1); __syncthreads(); chunk(2);
        CP_WAIT(0); __syncthreads(); chunk(3);

        // stage partials: accs[kh][n][m], n (0..63) stride 33
#pragma unroll
        for (int f = 0; f < 4; f++) {
            int nl = wn + f * 8 + (lane & 3) * 2;
            int ml = wm + (lane >> 2);
            accs[nl * 33 + ml] = acc[f][0];
            accs[(nl + 1) * 33 + ml] = acc[f][1];
            accs[nl * 33 + ml + 8] = acc[f][2];
            accs[(nl + 1) * 33 + ml + 8] = acc[f][3];
        }
        __syncthreads();

        __half* hhn = g_hh[(t + 1) & 1];
#pragma unroll
        for (int s = 0; s < 2; s++) {
            int q = tid + s * 256;
            int bl = q >> 4, hl = q & 15;
            int b = b0 + bl, h = hchunk * 16 + hl;
            float ip = acc0[(0 + hl) * 33 + bl]  + acc1[(0 + hl) * 33 + bl]  + xsf[(0 * 32 + bl) * 16 + hl];
            float fp = acc0[(16 + hl) * 33 + bl] + acc1[(16 + hl) * 33 + bl] + xsf[(1 * 32 + bl) * 16 + hl];
            float gp = acc0[(32 + hl) * 33 + bl] + acc1[(32 + hl) * 33 + bl] + xsf[(2 * 32 + bl) * 16 + hl];
            float op = acc0[(48 + hl) * 33 + bl] + acc1[(48 + hl) * 33 + bl] + xsf[(3 * 32 + bl) * 16 + hl];
            float ig = 1.f / (1.f + expf(-ip));
            float fg = 1.f / (1.f + expf(-fp));
            float gv = tanhf(gp);
            float og = 1.f / (1.f + expf(-op));
            float cn = gv * ig + fg * creg[s];
            creg[s] = cn;
            float hn = og * tanhf(cn);
            hlast[s] = hn;
            hhn[b * 512 + h] = __float2half_rn(hn);   // h first: it's the cross-block dependency
        }

        // release h to the group ASAP; do out-stores + xs prefetch while others arrive
        __threadfence();
        __syncthreads();
        if (tid == 0) atomicAdd(&g_cnt4[bchunk * 32], 1u);

#pragma unroll
        for (int s = 0; s < 2; s++) {
            int q = tid + s * 256;
            int bl = q >> 4, hl = q & 15;
            out[((size_t)(b0 + bl) * 512 + t) * 512 + hchunk * 16 + hl] = hlast[s];
        }
        int tp1 = (t < 511) ? (t + 1) : 511;
        prefetch_xs(tp1, (t + 1) & 1);
        CP_COMMIT();

        if (tid == 0) {
            unsigned tgt = (unsigned)(t + 1) * 32u;
            while (*(volatile unsigned*)&g_cnt4[bchunk * 32] < tgt) { __nanosleep(32); }
        }
        __syncthreads();
    }

#pragma unroll
    for (int s = 0; s < 2; s++) {
        int q = tid + s * 256;
        int bl = q >> 4, hl = q & 15;
        size_t idx = (size_t)(b0 + bl) * 512 + hchunk * 16 + hl;
        out[33554432 + idx] = hlast[s];
        out[33619968 + idx] = creg[s];
    }
}

extern "C" void kernel_launch(void* const* d_in, const int* in_sizes, int n_in,
                              void* d_out, int out_size) {
    const float* x  = (const float*)d_in[0];
    const float* h0 = (const float*)d_in[1];
    const float* c0 = (const float*)d_in[2];
    const float* We = (const float*)d_in[3];
    const float* be = (const float*)d_in[4];
    const float* Wf = (const float*)d_in[5];
    const float* bf = (const float*)d_in[6];
    const float* Wi = (const float*)d_in[7];
    const float* bi = (const float*)d_in[8];
    const float* Wg = (const float*)d_in[9];
    const float* bg = (const float*)d_in[10];
    const float* Wo = (const float*)d_in[11];
    const float* bo = (const float*)d_in[12];
    const float* Rf = (const float*)d_in[13];
    const float* Ri = (const float*)d_in[14];
    const float* Rg = (const float*)d_in[15];
    const float* Ro = (const float*)d_in[16];
    float* out = (float*)d_out;

    cudaFuncSetAttribute(xs_mm_kernel, cudaFuncAttributeMaxDynamicSharedMemorySize, XS_SMEM);
    cudaFuncSetAttribute(scan_mm_kernel, cudaFuncAttributeMaxDynamicSharedMemorySize, SC_SMEM);

    reset_kernel<<<1, 128>>>();
    wcomb_kernel<<<dim3(4, 32), 256>>>(Wi, Wf, Wg, Wo, We);
    bcomb_kernel<<<8, 256>>>(Wi, Wf, Wg, Wo, be, bi, bf, bg, bo);
    split_x_kernel<<<16384, 256>>>(x);
    split_w_kernel<<<512, 256>>>();
    split_h0_kernel<<<64, 256>>>(h0);
    split_R_kernel<<<1024, 256>>>(Ri, Rf, Rg, Ro);
    xs_mm_kernel<<<dim3(16, 512), 256, XS_SMEM>>>();
    scan_mm_kernel<<<128, 256, SC_SMEM>>>(c0, out);
}

// round 14
// speedup vs baseline: 1.4128x; 1.4128x over previous
#include <cuda_runtime.h>
#include <cuda_fp16.h>
#include <cstdint>

// B=128, T=512, DIM=256, E=512, H=512
// out = hidden_seq(33554432) + h_last at 33554432 + c_last at 33619968

__device__ __align__(16) float g_wcomb[2048 * 256];
__device__ __align__(16) float g_bcomb[2048];
__device__ __align__(16) float g_xs[134217728];      // [t][gate][b][h] fp32
__device__ __align__(16) __half g_xh[16777216];      // X fp16 [65536][256]
__device__ __align__(16) __half g_wch[524288];       // Wcomb hi [2048][256]
__device__ __align__(16) __half g_wcl[524288];       // Wcomb lo
__device__ __align__(16) __half g_rph[1048576];      // R fp16 packed [2048][512]; row=hc*64+gate*16+j <-> Rgate[hc*16+j]
__device__ __align__(16) __half g_hh[2][65536];      // h fp16 double buffer [b][k]
__device__ unsigned g_cnt4[128];                     // 4 group counters, stride 32 (128B apart)

// ---------- helpers ----------
__device__ __forceinline__ uint32_t smem_u32(const void* p) {
    uint32_t a;
    asm("{ .reg .u64 t; cvta.to.shared.u64 t, %1; cvt.u32.u64 %0, t; }" : "=r"(a) : "l"(p));
    return a;
}
__device__ __forceinline__ void ldm_x4(uint32_t* a, uint32_t addr) {
    asm volatile("ldmatrix.sync.aligned.m8n8.x4.shared.b16 {%0,%1,%2,%3}, [%4];"
                 : "=r"(a[0]), "=r"(a[1]), "=r"(a[2]), "=r"(a[3]) : "r"(addr));
}
__device__ __forceinline__ void mma16816(float* d, const uint32_t* a, uint32_t b0, uint32_t b1) {
    asm volatile("mma.sync.aligned.m16n8k16.row.col.f32.f16.f16.f32 "
                 "{%0,%1,%2,%3},{%4,%5,%6,%7},{%8,%9},{%0,%1,%2,%3};"
                 : "+f"(d[0]), "+f"(d[1]), "+f"(d[2]), "+f"(d[3])
                 : "r"(a[0]), "r"(a[1]), "r"(a[2]), "r"(a[3]), "r"(b0), "r"(b1));
}
__device__ __forceinline__ void cpa16(uint32_t saddr, const void* g) {
    asm volatile("cp.async.cg.shared.global [%0], [%1], 16;" :: "r"(saddr), "l"(g));
}
#define CP_COMMIT() asm volatile("cp.async.commit_group;" ::: "memory")
#define CP_WAIT(N)  asm volatile("cp.async.wait_group %0;" :: "n"(N) : "memory")

__device__ __forceinline__ void split1(float v, __half& h, __half& l) {
    h = __float2half_rn(v);
    l = __float2half_rn(v - __half2float(h));
}

// ---------- prep kernels ----------
__global__ void reset_kernel() {
    if (threadIdx.x < 128) g_cnt4[threadIdx.x] = 0u;
}

__global__ void wcomb_kernel(const float* __restrict__ Wi, const float* __restrict__ Wf,
                             const float* __restrict__ Wg, const float* __restrict__ Wo,
                             const float* __restrict__ We) {
    __shared__ float As[16][65];
    __shared__ float Bs[16][65];
    const int bm = blockIdx.y * 64, bn = blockIdx.x * 64, tid = threadIdx.x;
    const int tx = tid % 16, ty = tid / 16;
    float acc[4][4] = {};
    for (int k0 = 0; k0 < 512; k0 += 16) {
        for (int i = tid; i < 1024; i += 256) {
            int r = i / 16, kk = i % 16, row = bm + r, gate = row >> 9, h = row & 511;
            const float* W = (gate == 0) ? Wi : (gate == 1) ? Wf : (gate == 2) ? Wg : Wo;
            As[kk][r] = W[h * 512 + k0 + kk];
        }
        for (int i = tid; i < 1024; i += 256) {
            int kk = i / 64, c = i % 64;
            Bs[kk][c] = We[(k0 + kk) * 256 + bn + c];
        }
        __syncthreads();
#pragma unroll
        for (int kk = 0; kk < 16; kk++) {
            float a[4], b[4];
#pragma unroll
            for (int i = 0; i < 4; i++) a[i] = As[kk][ty * 4 + i];
#pragma unroll
            for (int j = 0; j < 4; j++) b[j] = Bs[kk][tx * 4 + j];
#pragma unroll
            for (int i = 0; i < 4; i++)
#pragma unroll
                for (int j = 0; j < 4; j++) acc[i][j] += a[i] * b[j];
        }
        __syncthreads();
    }
#pragma unroll
    for (int i = 0; i < 4; i++)
#pragma unroll
        for (int j = 0; j < 4; j++)
            g_wcomb[(bm + ty * 4 + i) * 256 + bn + tx * 4 + j] = acc[i][j];
}

__global__ void bcomb_kernel(const float* __restrict__ Wi, const float* __restrict__ Wf,
                             const float* __restrict__ Wg, const float* __restrict__ Wo,
                             const float* __restrict__ be,
                             const float* __restrict__ bi, const float* __restrict__ bf,
                             const float* __restrict__ bg, const float* __restrict__ bo) {
    int r = blockIdx.x * 256 + threadIdx.x;
    if (r >= 2048) return;
    int gate = r >> 9, h = r & 511;
    const float* W = (gate == 0) ? Wi : (gate == 1) ? Wf : (gate == 2) ? Wg : Wo;
    const float* bb = (gate == 0) ? bi : (gate == 1) ? bf : (gate == 2) ? bg : bo;
    float s = 0.f;
    for (int e = 0; e < 512; e++) s += W[h * 512 + e] * be[e];
    g_bcomb[r] = s + bb[h];
}

__global__ void split_x_kernel(const float* __restrict__ x) {
    size_t i = ((size_t)blockIdx.x * 256 + threadIdx.x) * 4;
    float4 v = *(const float4*)(x + i);
    ((__half2*)(g_xh + i))[0] = __floats2half2_rn(v.x, v.y);
    ((__half2*)(g_xh + i))[1] = __floats2half2_rn(v.z, v.w);
}
__global__ void split_w_kernel() {
    size_t i = ((size_t)blockIdx.x * 256 + threadIdx.x) * 4;
    float4 v = *(const float4*)(g_wcomb + i);
    __half h0, h1, h2, h3, l0, l1, l2, l3;
    split1(v.x, h0, l0); split1(v.y, h1, l1); split1(v.z, h2, l2); split1(v.w, h3, l3);
    ((__half2*)(g_wch + i))[0] = __halves2half2(h0, h1);
    ((__half2*)(g_wch + i))[1] = __halves2half2(h2, h3);
    ((__half2*)(g_wcl + i))[0] = __halves2half2(l0, l1);
    ((__half2*)(g_wcl + i))[1] = __halves2half2(l2, l3);
}
__global__ void split_h0_kernel(const float* __restrict__ h0) {
    size_t i = ((size_t)blockIdx.x * 256 + threadIdx.x) * 4;
    float4 v = *(const float4*)(h0 + i);
    ((__half2*)(g_hh[0] + i))[0] = __floats2half2_rn(v.x, v.y);
    ((__half2*)(g_hh[0] + i))[1] = __floats2half2_rn(v.z, v.w);
}
__global__ void split_R_kernel(const float* __restrict__ Ri, const float* __restrict__ Rf,
                               const float* __restrict__ Rg, const float* __restrict__ Ro) {
    size_t i = (size_t)blockIdx.x * 256 + threadIdx.x;   // 262144 quads
    int r = (int)(i >> 7), k = (int)(i & 127) * 4;
    int hc = r >> 6, w = r & 63, gate = w >> 4, j = w & 15;
    int h = hc * 16 + j;
    const float* R = (gate == 0) ? Ri : (gate == 1) ? Rf : (gate == 2) ? Rg : Ro;
    float4 v = *(const float4*)(R + (size_t)h * 512 + k);
    ((__half2*)(g_rph + (size_t)r * 512 + k))[0] = __floats2half2_rn(v.x, v.y);
    ((__half2*)(g_rph + (size_t)r * 512 + k))[1] = __floats2half2_rn(v.z, v.w);
}

// ---------- xs GEMM: X fp16 x W split-fp16 (2 terms, unchanged from R12) ----------
#define XS_SMEM 110592
__global__ void __launch_bounds__(256) xs_mm_kernel() {
    extern __shared__ __half xsm[];
    uint32_t sb = smem_u32(xsm);
    const int tid = threadIdx.x, lane = tid & 31, wid = tid >> 5;
    const int bn = blockIdx.x * 128, bm = blockIdx.y * 128;
    const int wm = (wid & 1) * 64, wn = (wid >> 1) * 32;

    float acc[4][4][4] = {};

    auto load_kc = [&](int kc) {
        uint32_t base = (kc & 1) * 27648;
        const int kcol = kc * 64;
#pragma unroll
        for (int q = 0; q < 4; q++) {
            int idx = tid + q * 256, r = idx >> 3, u = idx & 7;
            size_t ga = (size_t)(bm + r) * 256 + kcol + u * 8;
            size_t gb = (size_t)(bn + r) * 256 + kcol + u * 8;
            uint32_t so = (base + r * 72 + u * 8) * 2;
            cpa16(sb + so, g_xh + ga);
            cpa16(sb + so + 18432, g_wch + gb);
            cpa16(sb + so + 36864, g_wcl + gb);
        }
    };

    load_kc(0);
    CP_COMMIT();
    for (int kc = 0; kc < 4; kc++) {
        if (kc < 3) { load_kc(kc + 1); CP_COMMIT(); CP_WAIT(1); }
        else        { CP_WAIT(0); }
        __syncthreads();
        const uint32_t ah = sb + ((kc & 1) * 27648) * 2;
        const uint32_t bhb = ah + 18432, blb = ah + 36864;
        const uint32_t aoff = (wm + (lane & 15)) * 72 + ((lane >> 4) << 3);
        const uint32_t boff0 = (wn + ((lane >> 4) << 3) + (lane & 7)) * 72 + (((lane >> 3) & 1) << 3);
        const uint32_t boff1 = boff0 + 16 * 72;
#pragma unroll
        for (int kk = 0; kk < 64; kk += 16) {
            uint32_t bh01[4], bh23[4], bl01[4], bl23[4];
            ldm_x4(bh01, bhb + (boff0 + kk) * 2);
            ldm_x4(bh23, bhb + (boff1 + kk) * 2);
            ldm_x4(bl01, blb + (boff0 + kk) * 2);
            ldm_x4(bl23, blb + (boff1 + kk) * 2);
#pragma unroll
            for (int i = 0; i < 4; i++) {
                uint32_t ahi[4];
                ldm_x4(ahi, ah + (aoff + i * 16 * 72 + kk) * 2);
                mma16816(acc[i][0], ahi, bh01[0], bh01[1]);
                mma16816(acc[i][1], ahi, bh01[2], bh01[3]);
                mma16816(acc[i][2], ahi, bh23[0], bh23[1]);
                mma16816(acc[i][3], ahi, bh23[2], bh23[3]);
                mma16816(acc[i][0], ahi, bl01[0], bl01[1]);
                mma16816(acc[i][1], ahi, bl01[2], bl01[3]);
                mma16816(acc[i][2], ahi, bl23[0], bl23[1]);
                mma16816(acc[i][3], ahi, bl23[2], bl23[3]);
            }
        }
        __syncthreads();
    }

    const int gate = bn >> 9, hb = bn & 511;
#pragma unroll
    for (int f = 0; f < 4; f++) {
        int nl = wn + f * 8 + (lane & 3) * 2;
        float b0v = g_bcomb[bn + nl], b1v = g_bcomb[bn + nl + 1];
#pragma unroll
        for (int i = 0; i < 4; i++) {
            int m0 = bm + wm + i * 16 + (lane >> 2);
#pragma unroll
            for (int rr = 0; rr < 2; rr++) {
                int m = m0 + rr * 8;
                int t = m & 511, b = m >> 9;
                float2 v = make_float2(acc[i][f][rr * 2 + 0] + b0v, acc[i][f][rr * 2 + 1] + b1v);
                *(float2*)(g_xs + (((size_t)t * 4 + gate) * 128 + b) * 512 + hb + nl) = v;
            }
        }
    }
}

// ---------- persistent scan: R12 layout + double-buffered xs prefetch across the barrier ----------
// 128 blocks x 256 thr. Block=(bchunk: 32 batches, hchunk: 16 h x 4 gates = N64).
// smem halves: R @0 (64x520), h @33280 (32x520).
// bytes: accs @99840 (64x33 f32), xsbuf @108288 (2 x 8192). total 124672.
#define HS_OFF 33280
#define ACC_B 99840
#define XSB_B 108288
#define SC_SMEM 124672
__global__ void __launch_bounds__(256, 1) scan_mm_kernel(const float* __restrict__ c0,
                                                         float* __restrict__ out) {
    extern __shared__ __half ssm[];
    uint32_t sb = smem_u32(ssm);
    float* accs = (float*)((char*)ssm + ACC_B);
    const int tid = threadIdx.x, lane = tid & 31, wid = tid >> 5;
    const int bchunk = blockIdx.x >> 5, hchunk = blockIdx.x & 31;
    const int b0 = bchunk * 32;
    const int wm = (wid & 1) * 16, wn = (wid >> 1) * 16;

    // R resident (fp16)
#pragma unroll
    for (int q = 0; q < 16; q++) {
        int idx = tid + q * 256;
        int r = idx >> 6, u = idx & 63;
        const __half* src = g_rph + (size_t)(hchunk * 64 + r) * 512 + u * 8;
        *(uint4*)((char*)ssm + (r * 520 + u * 8) * 2) = *(const uint4*)src;
    }
    __syncthreads();

    float creg[2], hlast[2];
#pragma unroll
    for (int s = 0; s < 2; s++) {
        int q = tid + s * 256;
        int bl = q >> 4, hl = q & 15;
        creg[s] = c0[(b0 + bl) * 512 + hchunk * 16 + hl];
        hlast[s] = 0.f;
    }

    const uint32_t arow = (wm + (lane & 15)) * 520 + ((lane >> 4) << 3);
    const uint32_t brow = (wn + ((lane >> 4) << 3) + (lane & 7)) * 520 + (((lane >> 3) & 1) << 3);

    auto prefetch_xs = [&](int t, int buf) {
#pragma unroll
        for (int q = 0; q < 2; q++) {
            int idx = tid + q * 256;
            int gate = idx >> 7, w = idx & 127, bl = w >> 2, p = w & 3;
            const float* src = g_xs + (size_t)t * 262144 + (size_t)gate * 65536
                             + (size_t)(b0 + bl) * 512 + hchunk * 16 + p * 4;
            cpa16(sb + XSB_B + buf * 8192 + ((gate * 32 + bl) * 16 + p * 4) * 4, src);
        }
    };

    // preload xs(0) into buffer 0 -> exactly 1 group pending at every loop top
    prefetch_xs(0, 0);
    CP_COMMIT();

    for (int t = 0; t < 512; t++) {
        const __half* hhp = g_hh[t & 1];
        float* xsf = (float*)((char*)ssm + XSB_B + (t & 1) * 8192);

        auto load_h = [&](int c) {
#pragma unroll
            for (int q = 0; q < 2; q++) {
                int idx = tid + q * 256;
                int r = idx >> 4, u = idx & 15;
                const __half* src = hhp + (size_t)(b0 + r) * 512 + c * 128 + u * 8;
                cpa16(sb + (HS_OFF + r * 520 + c * 128 + u * 8) * 2, src);
            }
        };
        load_h(0); CP_COMMIT();
        load_h(1); CP_COMMIT();
        load_h(2); CP_COMMIT();
        load_h(3); CP_COMMIT();

        float acc[2][4] = {};
        auto chunk = [&](int c) {
            const int kb = c * 128;
#pragma unroll
            for (int k8 = 0; k8 < 8; k8++) {
                int kk = kb + k8 * 16;
                uint32_t ahi[4], bh[4];
                ldm_x4(ahi, sb + (HS_OFF + arow + kk) * 2);
                ldm_x4(bh, sb + (brow + kk) * 2);
                mma16816(acc[0], ahi, bh[0], bh[1]);
                mma16816(acc[1], ahi, bh[2], bh[3]);
            }
        };
        // pending: [xs(t) (long since issued), h0, h1, h2, h3]
        CP_WAIT(3); __syncthreads(); chunk(0);   // drains xs(t) + h0
        CP_WAIT(2); __syncthreads(); chunk(1);
        CP_WAIT(1); __syncthreads(); chunk(2);
        CP_WAIT(0); __syncthreads(); chunk(3);

        // stage accums: accs[n][m], n = gate16 group col (0..63), m = b local, stride 33
#pragma unroll
        for (int f = 0; f < 2; f++) {
            int nl = wn + f * 8 + (lane & 3) * 2;
            int ml = wm + (lane >> 2);
            accs[nl * 33 + ml] = acc[f][0];
            accs[(nl + 1) * 33 + ml] = acc[f][1];
            accs[nl * 33 + ml + 8] = acc[f][2];
            accs[(nl + 1) * 33 + ml + 8] = acc[f][3];
        }
        __syncthreads();

        __half* hhn = g_hh[(t + 1) & 1];
#pragma unroll
        for (int s = 0; s < 2; s++) {
            int q = tid + s * 256;
            int bl = q >> 4, hl = q & 15;
            int b = b0 + bl, h = hchunk * 16 + hl;
            float ip = accs[(0 + hl) * 33 + bl]  + xsf[(0 * 32 + bl) * 16 + hl];
            float fp = accs[(16 + hl) * 33 + bl] + xsf[(1 * 32 + bl) * 16 + hl];
            float gp = accs[(32 + hl) * 33 + bl] + xsf[(2 * 32 + bl) * 16 + hl];
            float op = accs[(48 + hl) * 33 + bl] + xsf[(3 * 32 + bl) * 16 + hl];
            float ig = 1.f / (1.f + expf(-ip));
            float fg = 1.f / (1.f + expf(-fp));
            float gv = tanhf(gp);
            float og = 1.f / (1.f + expf(-op));
            float cn = gv * ig + fg * creg[s];
            creg[s] = cn;
            float hn = og * tanhf(cn);
            hlast[s] = hn;
            out[((size_t)b * 512 + t) * 512 + h] = hn;
            hhn[b * 512 + h] = __float2half_rn(hn);
        }

        // prefetch next step's xs into the other buffer before the barrier
        int tp1 = (t < 511) ? (t + 1) : 511;
        prefetch_xs(tp1, (t + 1) & 1);
        CP_COMMIT();

        // per-bchunk barrier (32 blocks share data; 4 independent groups)
        __threadfence();
        __syncthreads();
        if (tid == 0) {
            unsigned tgt = (unsigned)(t + 1) * 32u;
            atomicAdd(&g_cnt4[bchunk * 32], 1u);
            while (*(volatile unsigned*)&g_cnt4[bchunk * 32] < tgt) { __nanosleep(32); }
        }
        __syncthreads();
    }

#pragma unroll
    for (int s = 0; s < 2; s++) {
        int q = tid + s * 256;
        int bl = q >> 4, hl = q & 15;
        size_t idx = (size_t)(b0 + bl) * 512 + hchunk * 16 + hl;
        out[33554432 + idx] = hlast[s];
        out[33619968 + idx] = creg[s];
    }
}

extern "C" void kernel_launch(void* const* d_in, const int* in_sizes, int n_in,
                              void* d_out, int out_size) {
    const float* x  = (const float*)d_in[0];
    const float* h0 = (const float*)d_in[1];
    const float* c0 = (const float*)d_in[2];
    const float* We = (const float*)d_in[3];
    const float* be = (const float*)d_in[4];
    const float* Wf = (const float*)d_in[5];
    const float* bf = (const float*)d_in[6];
    const float* Wi = (const float*)d_in[7];
    const float* bi = (const float*)d_in[8];
    const float* Wg = (const float*)d_in[9];
    const float* bg = (const float*)d_in[10];
    const float* Wo = (const float*)d_in[11];
    const float* bo = (const float*)d_in[12];
    const float* Rf = (const float*)d_in[13];
    const float* Ri = (const float*)d_in[14];
    const float* Rg = (const float*)d_in[15];
    const float* Ro = (const float*)d_in[16];
    float* out = (float*)d_out;

    cudaFuncSetAttribute(xs_mm_kernel, cudaFuncAttributeMaxDynamicSharedMemorySize, XS_SMEM);
    cudaFuncSetAttribute(scan_mm_kernel, cudaFuncAttributeMaxDynamicSharedMemorySize, SC_SMEM);

    reset_kernel<<<1, 128>>>();
    wcomb_kernel<<<dim3(4, 32), 256>>>(Wi, Wf, Wg, Wo, We);
    bcomb_kernel<<<8, 256>>>(Wi, Wf, Wg, Wo, be, bi, bf, bg, bo);
    split_x_kernel<<<16384, 256>>>(x);
    split_w_kernel<<<512, 256>>>();
    split_h0_kernel<<<64, 256>>>(h0);
    split_R_kernel<<<1024, 256>>>(Ri, Rf, Rg, Ro);
    xs_mm_kernel<<<dim3(16, 512), 256, XS_SMEM>>>();
    scan_mm_kernel<<<128, 256, SC_SMEM>>>(c0, out);
}

// round 17
// speedup vs baseline: 1.4780x; 1.0461x over previous
#include <cuda_runtime.h>
#include <cuda_fp16.h>
#include <cstdint>

// B=128, T=512, DIM=256, E=512, H=512
// out = hidden_seq(33554432) + h_last at 33554432 + c_last at 33619968

__device__ __align__(16) float g_wcomb[2048 * 256];
__device__ __align__(16) float g_bcomb[2048];
__device__ __align__(16) float g_xs[134217728];      // [t][gate][b][h] fp32
__device__ __align__(16) __half g_xh[16777216];      // X fp16 [65536][256]
__device__ __align__(16) __half g_wch[524288];       // Wcomb hi [2048][256]
__device__ __align__(16) __half g_wcl[524288];       // Wcomb lo
__device__ __align__(16) __half g_rph[1048576];      // R fp16 packed [2048][512]; row=hc*64+gate*16+j <-> Rgate[hc*16+j]
__device__ __align__(16) __half g_hh[2][65536];      // h fp16 double buffer [b][k]
__device__ unsigned g_cnt4[128];                     // 4 group counters, stride 32 (128B apart)

// ---------- helpers ----------
__device__ __forceinline__ uint32_t smem_u32(const void* p) {
    uint32_t a;
    asm("{ .reg .u64 t; cvta.to.shared.u64 t, %1; cvt.u32.u64 %0, t; }" : "=r"(a) : "l"(p));
    return a;
}
__device__ __forceinline__ void ldm_x4(uint32_t* a, uint32_t addr) {
    asm volatile("ldmatrix.sync.aligned.m8n8.x4.shared.b16 {%0,%1,%2,%3}, [%4];"
                 : "=r"(a[0]), "=r"(a[1]), "=r"(a[2]), "=r"(a[3]) : "r"(addr));
}
__device__ __forceinline__ void mma16816(float* d, const uint32_t* a, uint32_t b0, uint32_t b1) {
    asm volatile("mma.sync.aligned.m16n8k16.row.col.f32.f16.f16.f32 "
                 "{%0,%1,%2,%3},{%4,%5,%6,%7},{%8,%9},{%0,%1,%2,%3};"
                 : "+f"(d[0]), "+f"(d[1]), "+f"(d[2]), "+f"(d[3])
                 : "r"(a[0]), "r"(a[1]), "r"(a[2]), "r"(a[3]), "r"(b0), "r"(b1));
}
__device__ __forceinline__ void cpa16(uint32_t saddr, const void* g) {
    asm volatile("cp.async.cg.shared.global [%0], [%1], 16;" :: "r"(saddr), "l"(g));
}
#define CP_COMMIT() asm volatile("cp.async.commit_group;" ::: "memory")
#define CP_WAIT(N)  asm volatile("cp.async.wait_group %0;" :: "n"(N) : "memory")

__device__ __forceinline__ void split1(float v, __half& h, __half& l) {
    h = __float2half_rn(v);
    l = __float2half_rn(v - __half2float(h));
}

// ---------- prep kernels ----------
__global__ void reset_kernel() {
    if (threadIdx.x < 128) g_cnt4[threadIdx.x] = 0u;
}

__global__ void wcomb_kernel(const float* __restrict__ Wi, const float* __restrict__ Wf,
                             const float* __restrict__ Wg, const float* __restrict__ Wo,
                             const float* __restrict__ We) {
    __shared__ float As[16][65];
    __shared__ float Bs[16][65];
    const int bm = blockIdx.y * 64, bn = blockIdx.x * 64, tid = threadIdx.x;
    const int tx = tid % 16, ty = tid / 16;
    float acc[4][4] = {};
    for (int k0 = 0; k0 < 512; k0 += 16) {
        for (int i = tid; i < 1024; i += 256) {
            int r = i / 16, kk = i % 16, row = bm + r, gate = row >> 9, h = row & 511;
            const float* W = (gate == 0) ? Wi : (gate == 1) ? Wf : (gate == 2) ? Wg : Wo;
            As[kk][r] = W[h * 512 + k0 + kk];
        }
        for (int i = tid; i < 1024; i += 256) {
            int kk = i / 64, c = i % 64;
            Bs[kk][c] = We[(k0 + kk) * 256 + bn + c];
        }
        __syncthreads();
#pragma unroll
        for (int kk = 0; kk < 16; kk++) {
            float a[4], b[4];
#pragma unroll
            for (int i = 0; i < 4; i++) a[i] = As[kk][ty * 4 + i];
#pragma unroll
            for (int j = 0; j < 4; j++) b[j] = Bs[kk][tx * 4 + j];
#pragma unroll
            for (int i = 0; i < 4; i++)
#pragma unroll
                for (int j = 0; j < 4; j++) acc[i][j] += a[i] * b[j];
        }
        __syncthreads();
    }
#pragma unroll
    for (int i = 0; i < 4; i++)
#pragma unroll
        for (int j = 0; j < 4; j++)
            g_wcomb[(bm + ty * 4 + i) * 256 + bn + tx * 4 + j] = acc[i][j];
}

__global__ void bcomb_kernel(const float* __restrict__ Wi, const float* __restrict__ Wf,
                             const float* __restrict__ Wg, const float* __restrict__ Wo,
                             const float* __restrict__ be,
                             const float* __restrict__ bi, const float* __restrict__ bf,
                             const float* __restrict__ bg, const float* __restrict__ bo) {
    int r = blockIdx.x * 256 + threadIdx.x;
    if (r >= 2048) return;
    int gate = r >> 9, h = r & 511;
    const float* W = (gate == 0) ? Wi : (gate == 1) ? Wf : (gate == 2) ? Wg : Wo;
    const float* bb = (gate == 0) ? bi : (gate == 1) ? bf : (gate == 2) ? bg : bo;
    float s = 0.f;
    for (int e = 0; e < 512; e++) s += W[h * 512 + e] * be[e];
    g_bcomb[r] = s + bb[h];
}

__global__ void split_x_kernel(const float* __restrict__ x) {
    size_t i = ((size_t)blockIdx.x * 256 + threadIdx.x) * 4;
    float4 v = *(const float4*)(x + i);
    ((__half2*)(g_xh + i))[0] = __floats2half2_rn(v.x, v.y);
    ((__half2*)(g_xh + i))[1] = __floats2half2_rn(v.z, v.w);
}
__global__ void split_w_kernel() {
    size_t i = ((size_t)blockIdx.x * 256 + threadIdx.x) * 4;
    float4 v = *(const float4*)(g_wcomb + i);
    __half h0, h1, h2, h3, l0, l1, l2, l3;
    split1(v.x, h0, l0); split1(v.y, h1, l1); split1(v.z, h2, l2); split1(v.w, h3, l3);
    ((__half2*)(g_wch + i))[0] = __halves2half2(h0, h1);
    ((__half2*)(g_wch + i))[1] = __halves2half2(h2, h3);
    ((__half2*)(g_wcl + i))[0] = __halves2half2(l0, l1);
    ((__half2*)(g_wcl + i))[1] = __halves2half2(l2, l3);
}
__global__ void split_h0_kernel(const float* __restrict__ h0) {
    size_t i = ((size_t)blockIdx.x * 256 + threadIdx.x) * 4;
    float4 v = *(const float4*)(h0 + i);
    ((__half2*)(g_hh[0] + i))[0] = __floats2half2_rn(v.x, v.y);
    ((__half2*)(g_hh[0] + i))[1] = __floats2half2_rn(v.z, v.w);
}
__global__ void split_R_kernel(const float* __restrict__ Ri, const float* __restrict__ Rf,
                               const float* __restrict__ Rg, const float* __restrict__ Ro) {
    size_t i = (size_t)blockIdx.x * 256 + threadIdx.x;   // 262144 quads
    int r = (int)(i >> 7), k = (int)(i & 127) * 4;
    int hc = r >> 6, w = r & 63, gate = w >> 4, j = w & 15;
    int h = hc * 16 + j;
    const float* R = (gate == 0) ? Ri : (gate == 1) ? Rf : (gate == 2) ? Rg : Ro;
    float4 v = *(const float4*)(R + (size_t)h * 512 + k);
    ((__half2*)(g_rph + (size_t)r * 512 + k))[0] = __floats2half2_rn(v.x, v.y);
    ((__half2*)(g_rph + (size_t)r * 512 + k))[1] = __floats2half2_rn(v.z, v.w);
}

// ---------- xs GEMM: X fp16 x W split-fp16 (2 terms, unchanged from R12) ----------
#define XS_SMEM 110592
__global__ void __launch_bounds__(256) xs_mm_kernel() {
    extern __shared__ __half xsm[];
    uint32_t sb = smem_u32(xsm);
    const int tid = threadIdx.x, lane = tid & 31, wid = tid >> 5;
    const int bn = blockIdx.x * 128, bm = blockIdx.y * 128;
    const int wm = (wid & 1) * 64, wn = (wid >> 1) * 32;

    float acc[4][4][4] = {};

    auto load_kc = [&](int kc) {
        uint32_t base = (kc & 1) * 27648;
        const int kcol = kc * 64;
#pragma unroll
        for (int q = 0; q < 4; q++) {
            int idx = tid + q * 256, r = idx >> 3, u = idx & 7;
            size_t ga = (size_t)(bm + r) * 256 + kcol + u * 8;
            size_t gb = (size_t)(bn + r) * 256 + kcol + u * 8;
            uint32_t so = (base + r * 72 + u * 8) * 2;
            cpa16(sb + so, g_xh + ga);
            cpa16(sb + so + 18432, g_wch + gb);
            cpa16(sb + so + 36864, g_wcl + gb);
        }
    };

    load_kc(0);
    CP_COMMIT();
    for (int kc = 0; kc < 4; kc++) {
        if (kc < 3) { load_kc(kc + 1); CP_COMMIT(); CP_WAIT(1); }
        else        { CP_WAIT(0); }
        __syncthreads();
        const uint32_t ah = sb + ((kc & 1) * 27648) * 2;
        const uint32_t bhb = ah + 18432, blb = ah + 36864;
        const uint32_t aoff = (wm + (lane & 15)) * 72 + ((lane >> 4) << 3);
        const uint32_t boff0 = (wn + ((lane >> 4) << 3) + (lane & 7)) * 72 + (((lane >> 3) & 1) << 3);
        const uint32_t boff1 = boff0 + 16 * 72;
#pragma unroll
        for (int kk = 0; kk < 64; kk += 16) {
            uint32_t bh01[4], bh23[4], bl01[4], bl23[4];
            ldm_x4(bh01, bhb + (boff0 + kk) * 2);
            ldm_x4(bh23, bhb + (boff1 + kk) * 2);
            ldm_x4(bl01, blb + (boff0 + kk) * 2);
            ldm_x4(bl23, blb + (boff1 + kk) * 2);
#pragma unroll
            for (int i = 0; i < 4; i++) {
                uint32_t ahi[4];
                ldm_x4(ahi, ah + (aoff + i * 16 * 72 + kk) * 2);
                mma16816(acc[i][0], ahi, bh01[0], bh01[1]);
                mma16816(acc[i][1], ahi, bh01[2], bh01[3]);
                mma16816(acc[i][2], ahi, bh23[0], bh23[1]);
                mma16816(acc[i][3], ahi, bh23[2], bh23[3]);
                mma16816(acc[i][0], ahi, bl01[0], bl01[1]);
                mma16816(acc[i][1], ahi, bl01[2], bl01[3]);
                mma16816(acc[i][2], ahi, bl23[0], bl23[1]);
                mma16816(acc[i][3], ahi, bl23[2], bl23[3]);
            }
        }
        __syncthreads();
    }

    const int gate = bn >> 9, hb = bn & 511;
#pragma unroll
    for (int f = 0; f < 4; f++) {
        int nl = wn + f * 8 + (lane & 3) * 2;
        float b0v = g_bcomb[bn + nl], b1v = g_bcomb[bn + nl + 1];
#pragma unroll
        for (int i = 0; i < 4; i++) {
            int m0 = bm + wm + i * 16 + (lane >> 2);
#pragma unroll
            for (int rr = 0; rr < 2; rr++) {
                int m = m0 + rr * 8;
                int t = m & 511, b = m >> 9;
                float2 v = make_float2(acc[i][f][rr * 2 + 0] + b0v, acc[i][f][rr * 2 + 1] + b1v);
                *(float2*)(g_xs + (((size_t)t * 4 + gate) * 128 + b) * 512 + hb + nl) = v;
            }
        }
    }
}

// ---------- persistent scan: R12 layout; out-stores moved past the barrier arrive ----------
// 128 blocks x 256 thr. Block=(bchunk: 32 batches, hchunk: 16 h x 4 gates = N64).
// smem halves: R @0 (64x520), h @33280 (32x520).
// bytes: accs @99840 (64x33 f32), xsbuf @108288 (128x16 f32). total 116480.
#define HS_OFF 33280
#define ACC_B 99840
#define XSB_B 108288
#define SC_SMEM 116480
__global__ void __launch_bounds__(256, 1) scan_mm_kernel(const float* __restrict__ c0,
                                                         float* __restrict__ out) {
    extern __shared__ __half ssm[];
    uint32_t sb = smem_u32(ssm);
    float* accs = (float*)((char*)ssm + ACC_B);
    float* xsf = (float*)((char*)ssm + XSB_B);
    const int tid = threadIdx.x, lane = tid & 31, wid = tid >> 5;
    const int bchunk = blockIdx.x >> 5, hchunk = blockIdx.x & 31;
    const int b0 = bchunk * 32;
    const int wm = (wid & 1) * 16, wn = (wid >> 1) * 16;

    // R resident (fp16)
#pragma unroll
    for (int q = 0; q < 16; q++) {
        int idx = tid + q * 256;
        int r = idx >> 6, u = idx & 63;
        const __half* src = g_rph + (size_t)(hchunk * 64 + r) * 512 + u * 8;
        *(uint4*)((char*)ssm + (r * 520 + u * 8) * 2) = *(const uint4*)src;
    }
    __syncthreads();

    float creg[2], hlast[2];
#pragma unroll
    for (int s = 0; s < 2; s++) {
        int q = tid + s * 256;
        int bl = q >> 4, hl = q & 15;
        creg[s] = c0[(b0 + bl) * 512 + hchunk * 16 + hl];
        hlast[s] = 0.f;
    }

    const uint32_t arow = (wm + (lane & 15)) * 520 + ((lane >> 4) << 3);
    const uint32_t brow = (wn + ((lane >> 4) << 3) + (lane & 7)) * 520 + (((lane >> 3) & 1) << 3);

    for (int t = 0; t < 512; t++) {
        const __half* hhp = g_hh[t & 1];

        auto load_h = [&](int c) {
#pragma unroll
            for (int q = 0; q < 2; q++) {
                int idx = tid + q * 256;
                int r = idx >> 4, u = idx & 15;
                const __half* src = hhp + (size_t)(b0 + r) * 512 + c * 128 + u * 8;
                cpa16(sb + (HS_OFF + r * 520 + c * 128 + u * 8) * 2, src);
            }
        };
        load_h(0); CP_COMMIT();
        load_h(1); CP_COMMIT();
        // xs load for pointwise (independent of h)
#pragma unroll
        for (int q = 0; q < 2; q++) {
            int idx = tid + q * 256;
            int gate = idx >> 7, w = idx & 127, bl = w >> 2, p = w & 3;
            const float* src = g_xs + (size_t)t * 262144 + (size_t)gate * 65536
                             + (size_t)(b0 + bl) * 512 + hchunk * 16 + p * 4;
            cpa16(sb + XSB_B + ((gate * 32 + bl) * 16 + p * 4) * 4, src);
        }
        CP_COMMIT();
        load_h(2); CP_COMMIT();
        load_h(3); CP_COMMIT();

        float acc[2][4] = {};
        auto chunk = [&](int c) {
            const int kb = c * 128;
#pragma unroll
            for (int k8 = 0; k8 < 8; k8++) {
                int kk = kb + k8 * 16;
                uint32_t ahi[4], bh[4];
                ldm_x4(ahi, sb + (HS_OFF + arow + kk) * 2);
                ldm_x4(bh, sb + (brow + kk) * 2);
                mma16816(acc[0], ahi, bh[0], bh[1]);
                mma16816(acc[1], ahi, bh[2], bh[3]);
            }
        };
        CP_WAIT(4); __syncthreads(); chunk(0);
        CP_WAIT(3); __syncthreads(); chunk(1);
        CP_WAIT(1); __syncthreads(); chunk(2);
        CP_WAIT(0); __syncthreads(); chunk(3);

        // stage accums: accs[n][m], n = gate16 group col (0..63), m = b local, stride 33
#pragma unroll
        for (int f = 0; f < 2; f++) {
            int nl = wn + f * 8 + (lane & 3) * 2;
            int ml = wm + (lane >> 2);
            accs[nl * 33 + ml] = acc[f][0];
            accs[(nl + 1) * 33 + ml] = acc[f][1];
            accs[nl * 33 + ml + 8] = acc[f][2];
            accs[(nl + 1) * 33 + ml + 8] = acc[f][3];
        }
        __syncthreads();

        __half* hhn = g_hh[(t + 1) & 1];
        float ov[2];
#pragma unroll
        for (int s = 0; s < 2; s++) {
            int q = tid + s * 256;
            int bl = q >> 4, hl = q & 15;
            int b = b0 + bl, h = hchunk * 16 + hl;
            float ip = accs[(0 + hl) * 33 + bl]  + xsf[(0 * 32 + bl) * 16 + hl];
            float fp = accs[(16 + hl) * 33 + bl] + xsf[(1 * 32 + bl) * 16 + hl];
            float gp = accs[(32 + hl) * 33 + bl] + xsf[(2 * 32 + bl) * 16 + hl];
            float op = accs[(48 + hl) * 33 + bl] + xsf[(3 * 32 + bl) * 16 + hl];
            float ig = 1.f / (1.f + expf(-ip));
            float fg = 1.f / (1.f + expf(-fp));
            float gv = tanhf(gp);
            float og = 1.f / (1.f + expf(-op));
            float cn = gv * ig + fg * creg[s];
            creg[s] = cn;
            float hn = og * tanhf(cn);
            hlast[s] = hn;
            ov[s] = hn;
            hhn[b * 512 + h] = __float2half_rn(hn);   // ONLY h before the fence
        }

        // fence drains just the 2KB h writes; arrive; out-stores fill the barrier window
        __threadfence();
        __syncthreads();
        if (tid == 0) atomicAdd(&g_cnt4[bchunk * 32], 1u);

#pragma unroll
        for (int s = 0; s < 2; s++) {
            int q = tid + s * 256;
            int bl = q >> 4, hl = q & 15;
            out[((size_t)(b0 + bl) * 512 + t) * 512 + hchunk * 16 + hl] = ov[s];
        }

        if (tid == 0) {
            unsigned tgt = (unsigned)(t + 1) * 32u;
            while (*(volatile unsigned*)&g_cnt4[bchunk * 32] < tgt) { __nanosleep(32); }
        }
        __syncthreads();
    }

#pragma unroll
    for (int s = 0; s < 2; s++) {
        int q = tid + s * 256;
        int bl = q >> 4, hl = q & 15;
        size_t idx = (size_t)(b0 + bl) * 512 + hchunk * 16 + hl;
        out[33554432 + idx] = hlast[s];
        out[33619968 + idx] = creg[s];
    }
}

extern "C" void kernel_launch(void* const* d_in, const int* in_sizes, int n_in,
                              void* d_out, int out_size) {
    const float* x  = (const float*)d_in[0];
    const float* h0 = (const float*)d_in[1];
    const float* c0 = (const float*)d_in[2];
    const float* We = (const float*)d_in[3];
    const float* be = (const float*)d_in[4];
    const float* Wf = (const float*)d_in[5];
    const float* bf = (const float*)d_in[6];
    const float* Wi = (const float*)d_in[7];
    const float* bi = (const float*)d_in[8];
    const float* Wg = (const float*)d_in[9];
    const float* bg = (const float*)d_in[10];
    const float* Wo = (const float*)d_in[11];
    const float* bo = (const float*)d_in[12];
    const float* Rf = (const float*)d_in[13];
    const float* Ri = (const float*)d_in[14];
    const float* Rg = (const float*)d_in[15];
    const float* Ro = (const float*)d_in[16];
    float* out = (float*)d_out;

    cudaFuncSetAttribute(xs_mm_kernel, cudaFuncAttributeMaxDynamicSharedMemorySize, XS_SMEM);
    cudaFuncSetAttribute(scan_mm_kernel, cudaFuncAttributeMaxDynamicSharedMemorySize, SC_SMEM);

    reset_kernel<<<1, 128>>>();
    wcomb_kernel<<<dim3(4, 32), 256>>>(Wi, Wf, Wg, Wo, We);
    bcomb_kernel<<<8, 256>>>(Wi, Wf, Wg, Wo, be, bi, bf, bg, bo);
    split_x_kernel<<<16384, 256>>>(x);
    split_w_kernel<<<512, 256>>>();
    split_h0_kernel<<<64, 256>>>(h0);
    split_R_kernel<<<1024, 256>>>(Ri, Rf, Rg, Ro);
    xs_mm_kernel<<<dim3(16, 512), 256, XS_SMEM>>>();
    scan_mm_kernel<<<128, 256, SC_SMEM>>>(c0, out);
}